// round 3
// baseline (speedup 1.0000x reference)
#include <cuda_runtime.h>
#include <cuda_fp16.h>
#include <math.h>

// ----------------------------------------------------------------------------
// TimeSeriesRNN: 2-layer LSTM encoder (T=256) + decoder (T=32) with projection
// B=64, V=64, H=1024. Persistent-kernel, fp16 mma.m16n8k16, fragment-order
// global layouts (no smem / no ldmatrix in the hot loop).
// ----------------------------------------------------------------------------

#define B_    64
#define TIN   256
#define V_    64
#define H_    1024
#define TOUT  32
#define NCTA  128
#define NTHR  128     // 4 warps: warp w handles m-tile (rows of B) w

// Fragment-order device buffers (all sized in __half elements)
__device__ __align__(16) __half g_W0f[4456448];   // 4096 x 1088, per-CTA/chunk/lane frag order
__device__ __align__(16) __half g_W1f[8388608];   // 4096 x 2048
__device__ __align__(16) __half g_Wff[65536];     // 64 x 1024
__device__ __align__(16) __half g_XF [1048576];   // x in A-frag order, per timestep
__device__ __align__(16) __half g_H0F[131072];    // ping-pong h0 (2 bufs x 64x1024)
__device__ __align__(16) __half g_H1F[131072];    // ping-pong h1
__device__ __align__(16) __half g_INPF[4096];     // decoder feedback input (A-frag order)

// grid barrier state (zero-initialized at module load; count returns to 0)
__device__ unsigned g_bar_count = 0;
__device__ unsigned g_bar_gen   = 0;

// ----------------------------------------------------------------------------
// helpers
// ----------------------------------------------------------------------------
__device__ __forceinline__ void mma16816(float* d, const uint4& a,
                                         unsigned b0, unsigned b1) {
    asm volatile(
        "mma.sync.aligned.m16n8k16.row.col.f32.f16.f16.f32 "
        "{%0,%1,%2,%3}, {%4,%5,%6,%7}, {%8,%9}, {%0,%1,%2,%3};\n"
        : "+f"(d[0]), "+f"(d[1]), "+f"(d[2]), "+f"(d[3])
        : "r"(a.x), "r"(a.y), "r"(a.z), "r"(a.w), "r"(b0), "r"(b1));
}

__device__ __forceinline__ float sigm(float x) { return 1.0f / (1.0f + __expf(-x)); }

__device__ __forceinline__ void grid_sync() {
    __syncthreads();
    if (threadIdx.x == 0) {
        unsigned gen;
        asm volatile("ld.acquire.gpu.u32 %0, [%1];" : "=r"(gen) : "l"(&g_bar_gen) : "memory");
        __threadfence();
        unsigned t = atomicAdd(&g_bar_count, 1u);
        if (t == gridDim.x - 1) {
            g_bar_count = 0;
            asm volatile("st.release.gpu.u32 [%0], %1;" :: "l"(&g_bar_gen), "r"(gen + 1u) : "memory");
        } else {
            unsigned cur;
            do {
                asm volatile("ld.acquire.gpu.u32 %0, [%1];" : "=r"(cur) : "l"(&g_bar_gen) : "memory");
            } while (cur == gen);
        }
        __threadfence();
    }
    __syncthreads();
}

// ----------------------------------------------------------------------------
// prep kernels: rewrite operands into exact mma-fragment order (fp32 -> fp16)
// B-frag layout per (ct, chunk, ngroup): 32 lanes x 8 halfs:
//   half index q*2+e in lane l -> n = 16*ng + 8*(q>>1) + l/4
//                                 k = 16*c  + 8*(q&1)  + (l&3)*2 + e
// gate-interleaved row permutation: global row n_new = j*4 + gate
// ----------------------------------------------------------------------------
__global__ void prep_w0_kernel(const float* __restrict__ W) {
    const int total = 4456448, K = 1088, nchunk = 68;
    for (int f = blockIdx.x * blockDim.x + threadIdx.x; f < total; f += gridDim.x * blockDim.x) {
        int e = f & 1, q = (f >> 1) & 3, l = (f >> 3) & 31, ng = (f >> 8) & 1;
        int rest = f >> 9;
        int c = rest % nchunk, ct = rest / nchunk;
        int n = (ng << 4) + ((q >> 1) << 3) + (l >> 2);
        int k = (c << 4) + ((q & 1) << 3) + ((l & 3) << 1) + e;
        int j = (ct << 3) + (n >> 2);
        int gate = n & 3;
        g_W0f[f] = __float2half(W[(size_t)(gate * 1024 + j) * K + k]);
    }
}

__global__ void prep_w1_kernel(const float* __restrict__ W) {
    const int total = 8388608, K = 2048, nchunk = 128;
    for (int f = blockIdx.x * blockDim.x + threadIdx.x; f < total; f += gridDim.x * blockDim.x) {
        int e = f & 1, q = (f >> 1) & 3, l = (f >> 3) & 31, ng = (f >> 8) & 1;
        int rest = f >> 9;
        int c = rest & 127, ct = rest >> 7;
        int n = (ng << 4) + ((q >> 1) << 3) + (l >> 2);
        int k = (c << 4) + ((q & 1) << 3) + ((l & 3) << 1) + e;
        int j = (ct << 3) + (n >> 2);
        int gate = n & 3;
        g_W1f[f] = __float2half(W[(size_t)(gate * 1024 + j) * K + k]);
    }
}

__global__ void prep_wf_kernel(const float* __restrict__ Wf) {
    const int total = 65536;
    for (int f = blockIdx.x * blockDim.x + threadIdx.x; f < total; f += gridDim.x * blockDim.x) {
        int e = f & 1, q = (f >> 1) & 3, l = (f >> 3) & 31;
        int rest = f >> 8;
        int c = rest & 63, vg = rest >> 6;
        int v = (vg << 4) + ((q >> 1) << 3) + (l >> 2);
        int j = (c << 4) + ((q & 1) << 3) + ((l & 3) << 1) + e;
        g_Wff[f] = __float2half(Wf[(size_t)v * 1024 + j]);
    }
}

// A-frag layout per (t, m, chunk): half q*2+e in lane l ->
//   b(row) = 16*m + 8*(q&1) + l/4 ;  col = 16*c + 8*(q>>1) + (l&3)*2 + e
__global__ void prep_x_kernel(const float* __restrict__ x) {
    const int total = 1048576;
    for (int f = blockIdx.x * blockDim.x + threadIdx.x; f < total; f += gridDim.x * blockDim.x) {
        int e = f & 1, q = (f >> 1) & 3, l = (f >> 3) & 31;
        int rest = f >> 8;
        int c = rest & 3, m = (rest >> 2) & 3, t = rest >> 4;
        int b = (m << 4) + ((q & 1) << 3) + (l >> 2);
        int v = (c << 4) + ((q >> 1) << 3) + ((l & 3) << 1) + e;
        g_XF[f] = __float2half(x[(size_t)(b * TIN + t) * V_ + v]);
    }
}

// ----------------------------------------------------------------------------
// one LSTM cell phase for this CTA: GEMM over two input segments, then cell
// nonlinearity; writes new h (fragment order) to hout. cr = 4 cell-state regs.
// ----------------------------------------------------------------------------
__device__ __forceinline__ void cell_phase(
    const __half* __restrict__ Wp0,
    const __half* __restrict__ A0, int n0,
    const __half* __restrict__ A1, int n1,
    const float*  __restrict__ bias,
    float* cr, __half* __restrict__ hout,
    int ct, int m, int lane)
{
    float acc[4][4];
#pragma unroll
    for (int i = 0; i < 4; ++i)
#pragma unroll
        for (int k = 0; k < 4; ++k) acc[i][k] = 0.0f;

    const __half* a  = A0 + lane * 8;
    const __half* wl = Wp0 + lane * 8;

#pragma unroll 4
    for (int c = 0; c < n0; ++c) {
        uint4 av = __ldg((const uint4*)a);
        uint4 w0 = __ldg((const uint4*)wl);
        uint4 w1 = __ldg((const uint4*)(wl + 256));
        mma16816(acc[0], av, w0.x, w0.y);
        mma16816(acc[1], av, w0.z, w0.w);
        mma16816(acc[2], av, w1.x, w1.y);
        mma16816(acc[3], av, w1.z, w1.w);
        a += 256; wl += 512;
    }
    a = A1 + lane * 8;
#pragma unroll 4
    for (int c = 0; c < n1; ++c) {
        uint4 av = __ldg((const uint4*)a);
        uint4 w0 = __ldg((const uint4*)wl);
        uint4 w1 = __ldg((const uint4*)(wl + 256));
        mma16816(acc[0], av, w0.x, w0.y);
        mma16816(acc[1], av, w0.z, w0.w);
        mma16816(acc[2], av, w1.x, w1.y);
        mma16816(acc[3], av, w1.z, w1.w);
        a += 256; wl += 512;
    }

    // epilogue: bias, gate exchange (i,f <-> c~,o via lane^1), LSTM update
    const bool hi = (lane & 1);
#pragma unroll
    for (int nt = 0; nt < 4; ++nt) {
        float d0 = acc[nt][0], d1 = acc[nt][1], d2 = acc[nt][2], d3 = acc[nt][3];
        int jl = 2 * nt + ((lane & 3) >> 1);
        int j  = ct * 8 + jl;
        int g0 = (lane & 1) * 2;
        float bv0 = __ldg(bias + g0 * 1024 + j);
        float bv1 = __ldg(bias + (g0 + 1) * 1024 + j);
        d0 += bv0; d1 += bv1; d2 += bv0; d3 += bv1;

        float sA = hi ? d0 : d2;
        float sB = hi ? d1 : d3;
        float rA = __shfl_xor_sync(0xffffffffu, sA, 1);
        float rB = __shfl_xor_sync(0xffffffffu, sB, 1);
        float gi = hi ? rA : d0;
        float gf = hi ? rB : d1;
        float gc = hi ? d2 : rA;
        float go = hi ? d3 : rB;

        float cn = sigm(gf) * cr[nt] + sigm(gi) * tanhf(gc);
        cr[nt] = cn;
        float h = sigm(go) * tanhf(cn);

        int b = m * 16 + (lane >> 2) + (hi ? 8 : 0);
        int ldst = ((b & 7) << 2) + ((j & 7) >> 1);
        int qq = (hi ? 1 : 0) + ((j & 8) ? 2 : 0);
        hout[(size_t)((b >> 4) * 64 + (j >> 4)) * 256 + ldst * 8 + qq * 2 + (j & 1)] =
            __float2half(h);
    }
}

// ----------------------------------------------------------------------------
// main persistent kernel: 256 encoder steps + 32 decoder steps (+projection)
// ----------------------------------------------------------------------------
__global__ void __launch_bounds__(NTHR, 1)
rnn_main_kernel(const float* __restrict__ b0, const float* __restrict__ b1,
                const float* __restrict__ bf, float* __restrict__ out)
{
    const int ct   = blockIdx.x;
    const int tid  = threadIdx.x;
    const int w    = tid >> 5;
    const int lane = tid & 31;
    const int m    = w;   // warp -> m-tile of B

    float c0r[4] = {0.f, 0.f, 0.f, 0.f};
    float c1r[4] = {0.f, 0.f, 0.f, 0.f};

    const __half* Wb0 = g_W0f + (size_t)ct * 68 * 512;
    const __half* Wb1 = g_W1f + (size_t)ct * 128 * 512;

    __shared__ float red[4][32][8];

    for (int s = 0; s < TIN + TOUT; ++s) {
        const int p   = s & 1;
        const bool dec = (s >= TIN);

        // ---- layer 0: input = [x_t | h0_old] ----
        const __half* a0base;
        if (!dec)            a0base = g_XF + (size_t)(s * 4 + m) * 4 * 256;
        else if (s == TIN)   a0base = g_XF + (size_t)(255 * 4 + m) * 4 * 256;
        else                 a0base = g_INPF + (size_t)m * 4 * 256;
        const __half* h0old = g_H0F + (size_t)(p * 4 + m) * 16384;
        __half* h0out = g_H0F + (size_t)(1 - p) * 65536;
        cell_phase(Wb0, a0base, 4, h0old, (s > 0) ? 64 : 0, b0, c0r, h0out, ct, m, lane);
        grid_sync();

        // ---- layer 1: input = [h0_new | h1_old] ----
        const __half* h0new = g_H0F + (size_t)((1 - p) * 4 + m) * 16384;
        const __half* h1old = g_H1F + (size_t)(p * 4 + m) * 16384;
        __half* h1out = g_H1F + (size_t)(1 - p) * 65536;
        cell_phase(Wb1, h0new, 64, h1old, (s > 0) ? 64 : 0, b1, c1r, h1out, ct, m, lane);
        grid_sync();

        // ---- decoder projection: out = h1 @ Wf^T + bf ----
        if (dec) {
            if (ct < 16) {
                const int mm = ct & 3, vg = ct >> 2;
                const __half* A  = g_H1F + (size_t)((1 - p) * 4 + mm) * 16384
                                   + (size_t)(w * 16) * 256 + lane * 8;
                const __half* Wp = g_Wff + (size_t)(vg * 64 + w * 16) * 256 + lane * 8;
                float pacc[8];
#pragma unroll
                for (int k = 0; k < 8; ++k) pacc[k] = 0.0f;
#pragma unroll 4
                for (int cc = 0; cc < 16; ++cc) {
                    uint4 av = __ldg((const uint4*)(A  + (size_t)cc * 256));
                    uint4 wv = __ldg((const uint4*)(Wp + (size_t)cc * 256));
                    mma16816(pacc + 0, av, wv.x, wv.y);
                    mma16816(pacc + 4, av, wv.z, wv.w);
                }
#pragma unroll
                for (int k = 0; k < 8; ++k) red[w][lane][k] = pacc[k];
                __syncthreads();
                if (w == 0) {
                    float fsum[8];
#pragma unroll
                    for (int k = 0; k < 8; ++k)
                        fsum[k] = red[0][lane][k] + red[1][lane][k]
                                + red[2][lane][k] + red[3][lane][k];
                    const int tdec = s - TIN;
#pragma unroll
                    for (int nt = 0; nt < 2; ++nt)
#pragma unroll
                        for (int rr = 0; rr < 2; ++rr)
#pragma unroll
                            for (int e2 = 0; e2 < 2; ++e2) {
                                int b = mm * 16 + (lane >> 2) + rr * 8;
                                int v = vg * 16 + nt * 8 + ((lane & 3) << 1) + e2;
                                float val = fsum[nt * 4 + rr * 2 + e2] + __ldg(bf + v);
                                out[(size_t)(b * TOUT + tdec) * V_ + v] = val;
                                g_INPF[(size_t)((b >> 4) * 4 + (v >> 4)) * 256
                                       + (((b & 7) << 2) + ((v & 7) >> 1)) * 8
                                       + (rr + ((v & 8) ? 2 : 0)) * 2 + (v & 1)] =
                                    __float2half(val);
                            }
                }
            }
            grid_sync();
        }
    }
}

// ----------------------------------------------------------------------------
extern "C" void kernel_launch(void* const* d_in, const int* in_sizes, int n_in,
                              void* d_out, int out_size) {
    const float* x  = (const float*)d_in[0];
    const float* W0 = (const float*)d_in[1];
    const float* b0 = (const float*)d_in[2];
    const float* W1 = (const float*)d_in[3];
    const float* b1 = (const float*)d_in[4];
    const float* Wf = (const float*)d_in[5];
    const float* bf = (const float*)d_in[6];
    float* out = (float*)d_out;

    prep_w0_kernel<<<2048, 256>>>(W0);
    prep_w1_kernel<<<4096, 256>>>(W1);
    prep_wf_kernel<<<64, 256>>>(Wf);
    prep_x_kernel<<<1024, 256>>>(x);
    rnn_main_kernel<<<NCTA, NTHR>>>(b0, b1, bf, out);
}